// round 4
// baseline (speedup 1.0000x reference)
#include <cuda_runtime.h>
#include <cuda_bf16.h>

// ValScores: per-class mean of preds rows (segment reduction by label) + EMA.
//   out[c,:] = cnt[c]>0 ? 0.1*mean_c(preds) + 0.9*val_preds[c,:] : val_preds[c,:]
//
// Pipeline (2 launches, all static mapping — NO global ticket atomics; the
// round-3 work-stealing ticket serialized at one L2 address and regressed):
//   k_scatter : fixed-capacity bucket scatter, KSUB=32 sub-cursors per class
//               (low per-address atomic contention). Cursor == count.
//   k_reduce  : grid = 2*C, 128 threads. CTA b handles class c=b>>1, column
//               half h=b&1 (500 cols => 2000B/row, 16B aligned). Finer CTA
//               granularity halves the straggler tail vs 1-CTA-per-class.
//               Row indices staged to smem; rows streamed with __ldcs float4
//               (4-row MLP); fused mean+EMA. Cursor reset done by the SECOND
//               of the two CTAs to arrive (per-class arrival counter) -> no
//               read/reset race; all device state returns to zero each replay.

#define C_MAX   1024
#define KSUB    32
#define CAP     64             // per sub-list capacity (expected ~4 +- 2)
#define SMAX    (KSUB * CAP)   // 2048 indices, 8KB smem
#define GAMMA   0.9f
#define ONE_MINUS_GAMMA 0.1f

__device__ int g_cursor[C_MAX * KSUB];        // zero-init at module load
__device__ int g_rowidx[C_MAX * KSUB * CAP];  // 8 MB scratch
__device__ int g_classdone[C_MAX];            // zero-init arrival counters

// ---------------------------------------------------------------------------
// Scatter: 1 int4 label load / thread; sub-cursor from element-index low bits.
// ---------------------------------------------------------------------------
__global__ __launch_bounds__(256) void k_scatter_v4(const int4* __restrict__ labels4, int n4) {
    int t = blockIdx.x * blockDim.x + threadIdx.x;
    if (t >= n4) return;
    int4 L = labels4[t];
    int i0 = t * 4;

    int b0 = L.x * KSUB + ((i0 + 0) & (KSUB - 1));
    int b1 = L.y * KSUB + ((i0 + 1) & (KSUB - 1));
    int b2 = L.z * KSUB + ((i0 + 2) & (KSUB - 1));
    int b3 = L.w * KSUB + ((i0 + 3) & (KSUB - 1));

    int p0 = atomicAdd(&g_cursor[b0], 1);
    int p1 = atomicAdd(&g_cursor[b1], 1);
    int p2 = atomicAdd(&g_cursor[b2], 1);
    int p3 = atomicAdd(&g_cursor[b3], 1);

    if (p0 < CAP) g_rowidx[b0 * CAP + p0] = i0 + 0;
    if (p1 < CAP) g_rowidx[b1 * CAP + p1] = i0 + 1;
    if (p2 < CAP) g_rowidx[b2 * CAP + p2] = i0 + 2;
    if (p3 < CAP) g_rowidx[b3 * CAP + p3] = i0 + 3;
}

__global__ __launch_bounds__(256) void k_scatter_s(const int* __restrict__ labels, int N) {
    int i = blockIdx.x * blockDim.x + threadIdx.x;
    if (i >= N) return;
    int b = labels[i] * KSUB + (i & (KSUB - 1));
    int p = atomicAdd(&g_cursor[b], 1);
    if (p < CAP) g_rowidx[b * CAP + p] = i;
}

// ---------------------------------------------------------------------------
// Half-class reduce: grid = 2*C, 128 threads. Requires C % 8 == 0, C <= 1024.
// ---------------------------------------------------------------------------
__global__ __launch_bounds__(128) void k_reduce_half(
    const float* __restrict__ preds,
    const float* __restrict__ val_preds,
    float* __restrict__ out,
    int C)
{
    int c     = blockIdx.x >> 1;
    int h     = blockIdx.x & 1;
    int tid   = threadIdx.x;
    int halfC = C >> 1;                    // multiple of 4
    int col4  = h * halfC + tid * 4;

    __shared__ int s_base[KSUB + 1];
    __shared__ int s_idx[SMAX];
    __shared__ int s_last;

    // Per-sub counts -> prefix (thread 0; 32 independent loads).
    if (tid == 0) {
        int tot = 0;
        #pragma unroll
        for (int s = 0; s < KSUB; ++s) {
            s_base[s] = tot;
            int cs = g_cursor[c * KSUB + s];
            tot += (cs < CAP ? cs : CAP);
        }
        s_base[KSUB] = tot;
    }
    __syncthreads();

    // Stage row indices into smem (compacted).
    #pragma unroll
    for (int s = 0; s < KSUB; ++s) {
        int lo = s_base[s], cs = s_base[s + 1] - lo;
        const int* src = &g_rowidx[(c * KSUB + s) * CAP];
        for (int j = tid; j < cs; j += 128) s_idx[lo + j] = src[j];
    }
    __syncthreads();

    // Both halves have latched cursors/indices. Second arriver resets state.
    if (tid == 0) s_last = atomicAdd(&g_classdone[c], 1);
    __syncthreads();
    if (s_last == 1) {
        if (tid < KSUB) g_cursor[c * KSUB + tid] = 0;
        if (tid == 0)   g_classdone[c] = 0;
    }

    int cnt = s_base[KSUB];
    if (tid * 4 >= halfC) return;

    float ax = 0.f, ay = 0.f, az = 0.f, aw = 0.f;
    int r = 0;
    // 4 independent 16B streaming loads in flight per thread.
    for (; r + 3 < cnt; r += 4) {
        const float4* p0 = (const float4*)(preds + (size_t)s_idx[r + 0] * C + col4);
        const float4* p1 = (const float4*)(preds + (size_t)s_idx[r + 1] * C + col4);
        const float4* p2 = (const float4*)(preds + (size_t)s_idx[r + 2] * C + col4);
        const float4* p3 = (const float4*)(preds + (size_t)s_idx[r + 3] * C + col4);
        float4 v0 = __ldcs(p0);
        float4 v1 = __ldcs(p1);
        float4 v2 = __ldcs(p2);
        float4 v3 = __ldcs(p3);
        ax += v0.x; ay += v0.y; az += v0.z; aw += v0.w;
        ax += v1.x; ay += v1.y; az += v1.z; aw += v1.w;
        ax += v2.x; ay += v2.y; az += v2.z; aw += v2.w;
        ax += v3.x; ay += v3.y; az += v3.z; aw += v3.w;
    }
    for (; r < cnt; ++r) {
        float4 v = __ldcs((const float4*)(preds + (size_t)s_idx[r] * C + col4));
        ax += v.x; ay += v.y; az += v.z; aw += v.w;
    }

    float4 vp = *(const float4*)(val_preds + (size_t)c * C + col4);
    float4 o;
    if (cnt > 0) {
        float inv = ONE_MINUS_GAMMA / (float)cnt;
        o.x = ax * inv + GAMMA * vp.x;
        o.y = ay * inv + GAMMA * vp.y;
        o.z = az * inv + GAMMA * vp.z;
        o.w = aw * inv + GAMMA * vp.w;
    } else {
        o = vp;
    }
    *(float4*)(out + (size_t)c * C + col4) = o;
}

// Scalar-column fallback (general C): 1 CTA per class, resets own cursors.
__global__ __launch_bounds__(256) void k_reduce_s(
    const float* __restrict__ preds,
    const float* __restrict__ val_preds,
    float* __restrict__ out,
    int C)
{
    int c   = blockIdx.x;
    int tid = threadIdx.x;

    __shared__ int s_base[KSUB + 1];
    __shared__ int s_idx[SMAX];

    if (tid == 0) {
        int tot = 0;
        #pragma unroll
        for (int s = 0; s < KSUB; ++s) {
            s_base[s] = tot;
            int cs = g_cursor[c * KSUB + s];
            tot += (cs < CAP ? cs : CAP);
        }
        s_base[KSUB] = tot;
    }
    __syncthreads();
    #pragma unroll
    for (int s = 0; s < KSUB; ++s) {
        int lo = s_base[s], cs = s_base[s + 1] - lo;
        const int* src = &g_rowidx[(c * KSUB + s) * CAP];
        for (int j = tid; j < cs; j += 256) s_idx[lo + j] = src[j];
    }
    __syncthreads();
    if (tid < KSUB) g_cursor[c * KSUB + tid] = 0;

    int cnt = s_base[KSUB];
    for (int col = tid; col < C; col += 256) {
        float acc = 0.f;
        for (int r = 0; r < cnt; ++r)
            acc += __ldcs(preds + (size_t)s_idx[r] * C + col);
        float vp = val_preds[(size_t)c * C + col];
        out[(size_t)c * C + col] =
            (cnt > 0) ? (ONE_MINUS_GAMMA * acc / (float)cnt + GAMMA * vp) : vp;
    }
}

extern "C" void kernel_launch(void* const* d_in, const int* in_sizes, int n_in,
                              void* d_out, int out_size) {
    const float* preds     = (const float*)d_in[0];
    const int*   labels    = (const int*)  d_in[1];
    const float* val_preds = (const float*)d_in[2];
    float*       out       = (float*)d_out;

    const int N = in_sizes[1];       // 131072
    const int C = in_sizes[0] / N;   // 1000

    if ((N & 3) == 0) {
        int n4 = N / 4;
        k_scatter_v4<<<(n4 + 255) / 256, 256>>>((const int4*)labels, n4);
    } else {
        k_scatter_s<<<(N + 255) / 256, 256>>>(labels, N);
    }

    // Half-class path needs: halfC % 4 == 0 (float4), halfC <= 128*4 cols.
    if ((C % 8) == 0 && C <= C_MAX) {
        k_reduce_half<<<2 * C, 128>>>(preds, val_preds, out, C);
    } else {
        k_reduce_s<<<C, 256>>>(preds, val_preds, out, C);
    }
}

// round 5
// speedup vs baseline: 1.2037x; 1.2037x over previous
#include <cuda_runtime.h>
#include <cuda_bf16.h>

// ValScores: per-class mean of preds rows (segment reduction by label) + EMA.
//   out[c,:] = cnt[c]>0 ? 0.1*mean_c(preds) + 0.9*val_preds[c,:] : val_preds[c,:]
//
// Lessons (R3/R4): one CTA must read ENTIRE contiguous 4000B rows (column
// splitting kills DRAM locality: 76%->54%); no single-address ticket atomics.
//
// Pipeline (2 launches):
//   k_scatter : fixed-capacity bucket scatter, KSUB=16 sub-cursors/class.
//   k_reduce  : grid = 2*C, 256 threads. CTA pair (2c,2c+1) splits class c's
//               row LIST in half — identical access pattern to the best
//               kernel (whole coalesced rows, __ldcs float4, 4-row MLP) but
//               2x finer task granularity + multi-wave HW backfill = smaller
//               straggler tail. Partials combined via arrival-rank protocol:
//               rank0 writes its 4KB partial to scratch and exits; rank1
//               (spins only on an already-running CTA -> no deadlock) adds,
//               runs the mean+EMA epilogue, and resets all per-class state
//               so every graph replay starts from zero.

#define C_MAX   1024
#define KSUB    16
#define CAP     128            // per sub-list capacity (expected ~8 +- 3)
#define SMAX    (KSUB * CAP)   // 2048 indices, 8KB smem
#define GAMMA   0.9f
#define ONE_MINUS_GAMMA 0.1f

__device__ int   g_cursor[C_MAX * KSUB];        // zero-init at module load
__device__ int   g_rowidx[C_MAX * KSUB * CAP];  // 8 MB scratch
__device__ int   g_rank[C_MAX];                 // zero-init arrival counters
__device__ int   g_flag[C_MAX];                 // zero-init "partial ready"
__device__ float g_partial[C_MAX * C_MAX];      // 4 MB partial sums

// ---------------------------------------------------------------------------
// Scatter: 1 int4 label load / thread; sub-cursor from element-index low bits.
// ---------------------------------------------------------------------------
__global__ __launch_bounds__(256) void k_scatter_v4(const int4* __restrict__ labels4, int n4) {
    int t = blockIdx.x * blockDim.x + threadIdx.x;
    if (t >= n4) return;
    int4 L = labels4[t];
    int i0 = t * 4;

    int b0 = L.x * KSUB + ((i0 + 0) & (KSUB - 1));
    int b1 = L.y * KSUB + ((i0 + 1) & (KSUB - 1));
    int b2 = L.z * KSUB + ((i0 + 2) & (KSUB - 1));
    int b3 = L.w * KSUB + ((i0 + 3) & (KSUB - 1));

    int p0 = atomicAdd(&g_cursor[b0], 1);
    int p1 = atomicAdd(&g_cursor[b1], 1);
    int p2 = atomicAdd(&g_cursor[b2], 1);
    int p3 = atomicAdd(&g_cursor[b3], 1);

    if (p0 < CAP) g_rowidx[b0 * CAP + p0] = i0 + 0;
    if (p1 < CAP) g_rowidx[b1 * CAP + p1] = i0 + 1;
    if (p2 < CAP) g_rowidx[b2 * CAP + p2] = i0 + 2;
    if (p3 < CAP) g_rowidx[b3 * CAP + p3] = i0 + 3;
}

__global__ __launch_bounds__(256) void k_scatter_s(const int* __restrict__ labels, int N) {
    int i = blockIdx.x * blockDim.x + threadIdx.x;
    if (i >= N) return;
    int b = labels[i] * KSUB + (i & (KSUB - 1));
    int p = atomicAdd(&g_cursor[b], 1);
    if (p < CAP) g_rowidx[b * CAP + p] = i;
}

// ---------------------------------------------------------------------------
// Row-split reduce: grid = 2*C, 256 threads. Thread t owns cols [4t,4t+3].
// ---------------------------------------------------------------------------
__global__ __launch_bounds__(256) void k_reduce_pair(
    const float* __restrict__ preds,
    const float* __restrict__ val_preds,
    float* __restrict__ out,
    int C)
{
    int c    = blockIdx.x >> 1;
    int half = blockIdx.x & 1;
    int tid  = threadIdx.x;
    int col4 = tid * 4;
    bool active = (col4 < C);

    __shared__ int s_base[KSUB + 1];
    __shared__ int s_idx[SMAX];
    __shared__ int s_rank;

    // Per-sub counts -> prefix (thread 0; 16 independent loads).
    if (tid == 0) {
        int tot = 0;
        #pragma unroll
        for (int s = 0; s < KSUB; ++s) {
            s_base[s] = tot;
            int cs = g_cursor[c * KSUB + s];
            tot += (cs < CAP ? cs : CAP);
        }
        s_base[KSUB] = tot;
    }
    __syncthreads();

    // Stage full compacted index list into smem (both halves stage all; tiny).
    #pragma unroll
    for (int s = 0; s < KSUB; ++s) {
        int lo = s_base[s], cs = s_base[s + 1] - lo;
        const int* src = &g_rowidx[(c * KSUB + s) * CAP];
        for (int j = tid; j < cs; j += 256) s_idx[lo + j] = src[j];
    }
    __syncthreads();

    int cnt = s_base[KSUB];
    int lo  = half ? (cnt >> 1) : 0;
    int hi  = half ? cnt        : (cnt >> 1);

    // Sum my half of the row list: whole contiguous 4000B rows, streaming.
    float ax = 0.f, ay = 0.f, az = 0.f, aw = 0.f;
    if (active) {
        int r = lo;
        for (; r + 3 < hi; r += 4) {
            const float4* p0 = (const float4*)(preds + (size_t)s_idx[r + 0] * C + col4);
            const float4* p1 = (const float4*)(preds + (size_t)s_idx[r + 1] * C + col4);
            const float4* p2 = (const float4*)(preds + (size_t)s_idx[r + 2] * C + col4);
            const float4* p3 = (const float4*)(preds + (size_t)s_idx[r + 3] * C + col4);
            float4 v0 = __ldcs(p0);
            float4 v1 = __ldcs(p1);
            float4 v2 = __ldcs(p2);
            float4 v3 = __ldcs(p3);
            ax += v0.x; ay += v0.y; az += v0.z; aw += v0.w;
            ax += v1.x; ay += v1.y; az += v1.z; aw += v1.w;
            ax += v2.x; ay += v2.y; az += v2.z; aw += v2.w;
            ax += v3.x; ay += v3.y; az += v3.z; aw += v3.w;
        }
        for (; r < hi; ++r) {
            float4 v = __ldcs((const float4*)(preds + (size_t)s_idx[r] * C + col4));
            ax += v.x; ay += v.y; az += v.z; aw += v.w;
        }
    }
    __syncthreads();

    // Arrival-rank protocol.
    if (tid == 0) s_rank = atomicAdd(&g_rank[c], 1);
    __syncthreads();

    float* part = &g_partial[(size_t)c * C_MAX];

    if (s_rank == 0) {
        // First arriver: publish partial, signal, exit.
        if (active) {
            float4 w = make_float4(ax, ay, az, aw);
            *(float4*)(part + col4) = w;
        }
        __threadfence();
        __syncthreads();
        if (tid == 0) atomicExch(&g_flag[c], 1);
        return;
    }

    // Second arriver: wait for partner's partial (partner is already running).
    if (tid == 0) {
        while (atomicAdd(&g_flag[c], 0) == 0) { }
    }
    __syncthreads();
    __threadfence();

    if (active) {
        float4 w = *(const float4*)(part + col4);
        ax += w.x; ay += w.y; az += w.z; aw += w.w;

        float4 vp = *(const float4*)(val_preds + (size_t)c * C + col4);
        float4 o;
        if (cnt > 0) {
            float inv = ONE_MINUS_GAMMA / (float)cnt;
            o.x = ax * inv + GAMMA * vp.x;
            o.y = ay * inv + GAMMA * vp.y;
            o.z = az * inv + GAMMA * vp.z;
            o.w = aw * inv + GAMMA * vp.w;
        } else {
            o = vp;
        }
        *(float4*)(out + (size_t)c * C + col4) = o;
    }

    // Reset all per-class state for the next graph replay (both CTAs have
    // finished reading cursors/flags by construction).
    if (tid < KSUB) g_cursor[c * KSUB + tid] = 0;
    if (tid == 0) { g_rank[c] = 0; g_flag[c] = 0; }
}

// Scalar-column fallback (general C): 1 CTA per class, resets own cursors.
__global__ __launch_bounds__(256) void k_reduce_s(
    const float* __restrict__ preds,
    const float* __restrict__ val_preds,
    float* __restrict__ out,
    int C)
{
    int c   = blockIdx.x;
    int tid = threadIdx.x;

    __shared__ int s_base[KSUB + 1];
    __shared__ int s_idx[SMAX];

    if (tid == 0) {
        int tot = 0;
        #pragma unroll
        for (int s = 0; s < KSUB; ++s) {
            s_base[s] = tot;
            int cs = g_cursor[c * KSUB + s];
            tot += (cs < CAP ? cs : CAP);
        }
        s_base[KSUB] = tot;
    }
    __syncthreads();
    #pragma unroll
    for (int s = 0; s < KSUB; ++s) {
        int lo = s_base[s], cs = s_base[s + 1] - lo;
        const int* src = &g_rowidx[(c * KSUB + s) * CAP];
        for (int j = tid; j < cs; j += 256) s_idx[lo + j] = src[j];
    }
    __syncthreads();
    if (tid < KSUB) g_cursor[c * KSUB + tid] = 0;

    int cnt = s_base[KSUB];
    for (int col = tid; col < C; col += 256) {
        float acc = 0.f;
        for (int r = 0; r < cnt; ++r)
            acc += __ldcs(preds + (size_t)s_idx[r] * C + col);
        float vp = val_preds[(size_t)c * C + col];
        out[(size_t)c * C + col] =
            (cnt > 0) ? (ONE_MINUS_GAMMA * acc / (float)cnt + GAMMA * vp) : vp;
    }
}

extern "C" void kernel_launch(void* const* d_in, const int* in_sizes, int n_in,
                              void* d_out, int out_size) {
    const float* preds     = (const float*)d_in[0];
    const int*   labels    = (const int*)  d_in[1];
    const float* val_preds = (const float*)d_in[2];
    float*       out       = (float*)d_out;

    const int N = in_sizes[1];       // 131072
    const int C = in_sizes[0] / N;   // 1000

    if ((N & 3) == 0) {
        int n4 = N / 4;
        k_scatter_v4<<<(n4 + 255) / 256, 256>>>((const int4*)labels, n4);
    } else {
        k_scatter_s<<<(N + 255) / 256, 256>>>(labels, N);
    }

    if ((C % 4) == 0 && C <= C_MAX) {
        k_reduce_pair<<<2 * C, 256>>>(preds, val_preds, out, C);
    } else {
        k_reduce_s<<<C, 256>>>(preds, val_preds, out, C);
    }
}